// round 4
// baseline (speedup 1.0000x reference)
#include <cuda_runtime.h>
#include <cstdint>

// x: (B=2, C=16, D=16, H=256, W=256) fp32
// out: (B=2, 4*C=64, D=16, 128, 128) fp32, subbands LL/HL/LH/HH at channel groups 0..3
//
// Per 2x2 block: x1=x[2i,2j]/2, x2=x[2i+1,2j]/2, x3=x[2i,2j+1]/2, x4=x[2i+1,2j+1]/2
//   LL =  x1+x2+x3+x4 ; HL = -x1-x2+x3+x4 ; LH = -x1+x2-x3+x4 ; HH = x1-x2-x3+x4

__global__ __launch_bounds__(256)
void dwt_haar_kernel(const float* __restrict__ x, float* __restrict__ out) {
    // Each thread: 8 adjacent 2x2 blocks along j (16 input cols, 2 input rows)
    // tid decomposition: [plane(9b)][i(7b)][j8(4b)] -> 512 * 128 * 16 = 1,048,576 threads
    const unsigned tid = blockIdx.x * blockDim.x + threadIdx.x;
    const unsigned j8    = tid & 15u;          // 0..15  (output col / 8)
    const unsigned i     = (tid >> 4) & 127u;  // 0..127 (output row)
    const unsigned plane = tid >> 11;          // 0..511 = b*256 + c*16 + d
    if (plane >= 512u) return;

    const unsigned b = plane >> 8;
    const unsigned c = (plane >> 4) & 15u;
    const unsigned d = plane & 15u;

    // ---- input: rows 2i, 2i+1, cols [16*j8, 16*j8+16) -- 8 streaming LDG.128, front-batched
    const float* in = x + (size_t)plane * 65536u + (size_t)(2u * i) * 256u + j8 * 16u;
    float4 r0[4], r1[4];
#pragma unroll
    for (int k = 0; k < 4; k++) r0[k] = __ldcs(reinterpret_cast<const float4*>(in) + k);
#pragma unroll
    for (int k = 0; k < 4; k++) r1[k] = __ldcs(reinterpret_cast<const float4*>(in + 256) + k);

    float4 ll[2], hl[2], lh[2], hh[2];

#pragma unroll
    for (int q = 0; q < 2; q++) {          // q: which output float4 (4 blocks each)
        const float* a0 = reinterpret_cast<const float*>(&r0[2 * q]);  // 8 floats row 0
        const float* a1 = reinterpret_cast<const float*>(&r1[2 * q]);  // 8 floats row 1
        float* pll = reinterpret_cast<float*>(&ll[q]);
        float* phl = reinterpret_cast<float*>(&hl[q]);
        float* plh = reinterpret_cast<float*>(&lh[q]);
        float* phh = reinterpret_cast<float*>(&hh[q]);
#pragma unroll
        for (int k = 0; k < 4; k++) {      // block within the 8-float span
            const float x1 = a0[2 * k]     * 0.5f;
            const float x3 = a0[2 * k + 1] * 0.5f;
            const float x2 = a1[2 * k]     * 0.5f;
            const float x4 = a1[2 * k + 1] * 0.5f;
            pll[k] =  x1 + x2 + x3 + x4;
            phl[k] = -x1 - x2 + x3 + x4;
            plh[k] = -x1 + x2 - x3 + x4;
            phh[k] =  x1 - x2 - x3 + x4;
        }
    }

    // ---- output: (b, g*16+c, d, i, j), plane 128*128; 2 float4 per subband stream
    const size_t gstride = (size_t)16 * 16 * 16384;   // +1 in subband group g
    const size_t ob = ((size_t)(b * 64u + c) * 16u + d) * 16384u
                    + (size_t)i * 128u + j8 * 8u;

    float4* o0 = reinterpret_cast<float4*>(out + ob);
    float4* o1 = reinterpret_cast<float4*>(out + ob + gstride);
    float4* o2 = reinterpret_cast<float4*>(out + ob + 2 * gstride);
    float4* o3 = reinterpret_cast<float4*>(out + ob + 3 * gstride);
    __stcs(o0,     ll[0]);  __stcs(o0 + 1, ll[1]);
    __stcs(o1,     hl[0]);  __stcs(o1 + 1, hl[1]);
    __stcs(o2,     lh[0]);  __stcs(o2 + 1, lh[1]);
    __stcs(o3,     hh[0]);  __stcs(o3 + 1, hh[1]);
}

extern "C" void kernel_launch(void* const* d_in, const int* in_sizes, int n_in,
                              void* d_out, int out_size) {
    const float* x = (const float*)d_in[0];
    float* out = (float*)d_out;
    const int total_threads = 512 * 128 * 16;   // 1,048,576
    const int block = 256;
    const int grid = total_threads / block;     // 4096
    dwt_haar_kernel<<<grid, block>>>(x, out);
}

// round 5
// speedup vs baseline: 1.1050x; 1.1050x over previous
#include <cuda_runtime.h>
#include <cstdint>

// x: (B=2, C=16, D=16, H=256, W=256) fp32
// out: (B=2, 4*C=64, D=16, 128, 128) fp32, subbands LL/HL/LH/HH at channel groups 0..3
//
// Per 2x2 block: x1=x[2i,2j]/2, x2=x[2i+1,2j]/2, x3=x[2i,2j+1]/2, x4=x[2i+1,2j+1]/2
//   LL =  x1+x2+x3+x4 ; HL = -x1-x2+x3+x4 ; LH = -x1+x2-x3+x4 ; HH = x1-x2-x3+x4

__global__ __launch_bounds__(256, 8)
void dwt_haar_kernel(const float* __restrict__ x, float* __restrict__ out) {
    // Each thread: 4 adjacent 2x2 blocks along j (8 input cols, 2 input rows)
    // tid decomposition: [plane(9b)][i(7b)][j4(5b)]  -> 512 * 128 * 32 = 2,097,152 threads
    const unsigned tid = blockIdx.x * blockDim.x + threadIdx.x;
    const unsigned j4    = tid & 31u;          // 0..31  (output col / 4)
    const unsigned i     = (tid >> 5) & 127u;  // 0..127 (output row)
    const unsigned plane = tid >> 12;          // 0..511 = b*256 + c*16 + d
    if (plane >= 512u) return;

    const unsigned b = plane >> 8;
    const unsigned c = (plane >> 4) & 15u;
    const unsigned d = plane & 15u;

    // ---- input: rows 2i and 2i+1, cols [8*j4, 8*j4+8) — 4 front-batched LDG.128
    const float* in = x + (size_t)plane * 65536u + (size_t)(2u * i) * 256u + j4 * 8u;
    const float4 r0a = *reinterpret_cast<const float4*>(in);
    const float4 r0b = *reinterpret_cast<const float4*>(in + 4);
    const float4 r1a = *reinterpret_cast<const float4*>(in + 256);
    const float4 r1b = *reinterpret_cast<const float4*>(in + 260);

    float4 ll, hl, lh, hh;

    {
        const float x1 = r0a.x * 0.5f, x3 = r0a.y * 0.5f;
        const float x2 = r1a.x * 0.5f, x4 = r1a.y * 0.5f;
        ll.x =  x1 + x2 + x3 + x4;
        hl.x = -x1 - x2 + x3 + x4;
        lh.x = -x1 + x2 - x3 + x4;
        hh.x =  x1 - x2 - x3 + x4;
    }
    {
        const float x1 = r0a.z * 0.5f, x3 = r0a.w * 0.5f;
        const float x2 = r1a.z * 0.5f, x4 = r1a.w * 0.5f;
        ll.y =  x1 + x2 + x3 + x4;
        hl.y = -x1 - x2 + x3 + x4;
        lh.y = -x1 + x2 - x3 + x4;
        hh.y =  x1 - x2 - x3 + x4;
    }
    {
        const float x1 = r0b.x * 0.5f, x3 = r0b.y * 0.5f;
        const float x2 = r1b.x * 0.5f, x4 = r1b.y * 0.5f;
        ll.z =  x1 + x2 + x3 + x4;
        hl.z = -x1 - x2 + x3 + x4;
        lh.z = -x1 + x2 - x3 + x4;
        hh.z =  x1 - x2 - x3 + x4;
    }
    {
        const float x1 = r0b.z * 0.5f, x3 = r0b.w * 0.5f;
        const float x2 = r1b.z * 0.5f, x4 = r1b.w * 0.5f;
        ll.w =  x1 + x2 + x3 + x4;
        hl.w = -x1 - x2 + x3 + x4;
        lh.w = -x1 + x2 - x3 + x4;
        hh.w =  x1 - x2 - x3 + x4;
    }

    // ---- output: (b, g*16+c, d, i, j) with plane 128*128 — 4 streaming STG.128
    const size_t gstride = (size_t)16 * 16 * 16384;   // +1 in subband group g
    const size_t ob = ((size_t)(b * 64u + c) * 16u + d) * 16384u
                    + (size_t)i * 128u + j4 * 4u;

    __stcs(reinterpret_cast<float4*>(out + ob),               ll);
    __stcs(reinterpret_cast<float4*>(out + ob + gstride),     hl);
    __stcs(reinterpret_cast<float4*>(out + ob + 2 * gstride), lh);
    __stcs(reinterpret_cast<float4*>(out + ob + 3 * gstride), hh);
}

extern "C" void kernel_launch(void* const* d_in, const int* in_sizes, int n_in,
                              void* d_out, int out_size) {
    const float* x = (const float*)d_in[0];
    float* out = (float*)d_out;
    const int total_threads = 512 * 128 * 32;   // 2,097,152
    const int block = 256;
    const int grid = total_threads / block;     // 8192
    dwt_haar_kernel<<<grid, block>>>(x, out);
}